// round 13
// baseline (speedup 1.0000x reference)
#include <cuda_runtime.h>
#include <math.h>

#define BB 16
#define SS 4096
#define FF 512
#define NC 10
#define TABSZ 8192
#define TABM  8191
#define HEMPTY 0xFFFFFFFFu   // negative-NaN pattern; impossible after canonicalization

// global scratch (static device arrays; no allocation)
__device__ int   g_perm[BB * SS];
__device__ int   g_offs[BB * (NC + 1)];
__device__ float g_fin[BB * 15 * FF];          // [b][q][f]
__device__ int   g_uniq[BB * FF];
__device__ float g_cols[(size_t)BB * FF * SS]; // transposed canonical columns

__device__ __forceinline__ unsigned hslot(unsigned x) {
    x *= 2654435761u;
    return (x >> 19) & TABM;
}

// ---------------------------------------------------------------------------
// Kernel 1: deterministic stable counting sort of y per batch (atomic-free)
// ---------------------------------------------------------------------------
__global__ void prep_kernel(const int* __restrict__ y) {
    __shared__ int histT[NC][256];
    __shared__ int curT[NC][256];
    __shared__ int offs[NC + 1];

    const int b = blockIdx.x;
    const int t = threadIdx.x;
    const int* yb = y + b * SS;
    const int base = t * 16;

#pragma unroll
    for (int c = 0; c < NC; c++) histT[c][t] = 0;
    __syncthreads();
#pragma unroll
    for (int j = 0; j < 16; j++) histT[yb[base + j]][t]++;
    __syncthreads();

    for (int d = 1; d < 256; d <<= 1) {
        int v[NC];
#pragma unroll
        for (int c = 0; c < NC; c++) v[c] = (t >= d) ? histT[c][t - d] : 0;
        __syncthreads();
#pragma unroll
        for (int c = 0; c < NC; c++) histT[c][t] += v[c];
        __syncthreads();
    }

    if (t == 0) {
        offs[0] = 0;
#pragma unroll
        for (int c = 0; c < NC; c++) offs[c + 1] = offs[c] + histT[c][255];
#pragma unroll
        for (int c = 0; c <= NC; c++) g_offs[b * (NC + 1) + c] = offs[c];
    }
    __syncthreads();
#pragma unroll
    for (int c = 0; c < NC; c++)
        curT[c][t] = offs[c] + (t > 0 ? histT[c][t - 1] : 0);
    __syncthreads();
#pragma unroll
    for (int j = 0; j < 16; j++) {
        int s = base + j;
        g_perm[b * SS + curT[yb[s]][t]++] = s;
    }
}

// ---------------------------------------------------------------------------
// Kernel 2: stats kernel — grid (FF/4, BB), 256 threads, 3 CTAs/SM.
// Single X pass: 5 stats + class sums; writes canonical columns to g_cols.
// ---------------------------------------------------------------------------
#define SM_VALS 0
#define SM_RED  65536                    // 20*8 floats
#define SM_OFFS (SM_RED + 640)           // 12 ints
#define SSMEM   (SM_OFFS + 48)

__global__ void __launch_bounds__(256, 3)
stats_kernel(const float* __restrict__ X) {
    extern __shared__ unsigned char sm[];
    float* vals  = (float*)(sm + SM_VALS);
    float* red   = (float*)(sm + SM_RED);
    int*   soffs = (int*)(sm + SM_OFFS);

    const int t  = threadIdx.x;
    const int fg = blockIdx.x, b = blockIdx.y;
    const int lane = t & 31, warp = t >> 5;

    if (t <= NC) soffs[t] = g_offs[b * (NC + 1) + t];

    // ----- Phase 1: load X once (16 independent LDG.128/thread) + 5 stats -----
    const float4* Xb = (const float4*)(X + (size_t)b * SS * FF);
    float s0[4] = {0,0,0,0}, s1[4] = {0,0,0,0}, s2[4] = {0,0,0,0};
    float s3[4] = {0,0,0,0}, s4[4] = {0,0,0,0};

#pragma unroll
    for (int k = 0; k < 16; k++) {
        const int s = k * 256 + t;
        const float4 x = __ldg(&Xb[(size_t)s * (FF / 4) + fg]);
        float xv[4] = {x.x, x.y, x.z, x.w};
#pragma unroll
        for (int f = 0; f < 4; f++) {
            float v = xv[f];
            const bool isn = (v != v);
            v = isn ? 0.f : v;
            v = (v == 0.f) ? 0.f : v;        // -0 -> +0
            const float a = fabsf(v);
            s0[f] += v;
            s1[f] += v * v;
            s2[f] += a;
            s3[f]  = fmaxf(s3[f], a);
            s4[f] += isn ? 1.f : 0.f;
            vals[f * SS + s] = v;
        }
    }

    // reduce 20 class-independent stats
#pragma unroll
    for (int q = 0; q < 20; q++) {
        float v;
        if (q < 4)       v = s0[q];
        else if (q < 8)  v = s1[q - 4];
        else if (q < 12) v = s2[q - 8];
        else if (q < 16) v = s3[q - 12];
        else             v = s4[q - 16];
        const bool ismax = (q >= 12 && q < 16);
#pragma unroll
        for (int o = 16; o; o >>= 1) {
            float w = __shfl_xor_sync(0xFFFFFFFFu, v, o);
            v = ismax ? fmaxf(v, w) : (v + w);
        }
        if (lane == 0) red[q * 8 + warp] = v;
    }
    __syncthreads();
    if (t < 20) {
        const bool ismax = ((t >> 2) == 3);
        float v = red[t * 8];
#pragma unroll
        for (int w = 1; w < 8; w++)
            v = ismax ? fmaxf(v, red[t * 8 + w]) : (v + red[t * 8 + w]);
        g_fin[((size_t)b * 15 + (t >> 2)) * FF + fg * 4 + (t & 3)] = v;
    }

    // ----- Phase 2: write transposed canonical columns (coalesced) -----
#pragma unroll
    for (int f = 0; f < 4; f++) {
        float4*       dst = (float4*)(g_cols + ((size_t)b * FF + fg * 4 + f) * SS);
        const float4* src = (const float4*)(vals + f * SS);
#pragma unroll
        for (int k = 0; k < 4; k++) dst[k * 256 + t] = src[k * 256 + t];
    }

    // ----- Phase 3: per-class sums from smem in perm order (2 groups of 5) -----
    const int* perm = g_perm + b * SS;
#pragma unroll 1
    for (int grp = 0; grp < 2; grp++) {
        float cls[5][4];
#pragma unroll
        for (int c = 0; c < 5; c++)
#pragma unroll
            for (int f = 0; f < 4; f++) cls[c][f] = 0.f;

#pragma unroll
        for (int c = 0; c < 5; c++) {
            const int cc = grp * 5 + c;
            const int lo = soffs[cc], hi = soffs[cc + 1];
            for (int i = lo + t; i < hi; i += 256) {
                const int s = __ldg(&perm[i]);
#pragma unroll
                for (int f = 0; f < 4; f++) cls[c][f] += vals[f * SS + s];
            }
        }
#pragma unroll
        for (int q = 0; q < 20; q++) {
            float v = cls[q >> 2][q & 3];
#pragma unroll
            for (int o = 16; o; o >>= 1)
                v += __shfl_xor_sync(0xFFFFFFFFu, v, o);
            if (lane == 0) red[q * 8 + warp] = v;
        }
        __syncthreads();
        if (t < 20) {
            float v = red[t * 8];
#pragma unroll
            for (int w = 1; w < 8; w++) v += red[t * 8 + w];
            const int c = grp * 5 + (t >> 2);
            g_fin[((size_t)b * 15 + 5 + c) * FF + fg * 4 + (t & 3)] = v;
        }
        __syncthreads();
    }
}

// ---------------------------------------------------------------------------
// Kernel 3: uniq kernel — one CTA per (f, b), 256 threads, 33KB smem,
// 5 CTAs/SM. Two insert halves; breadth-first 4-wide windowed verify-scan.
// ---------------------------------------------------------------------------
#define USMEM (TABSZ * 4 + 16)

__global__ void __launch_bounds__(256, 5)
uniq_kernel() {
    extern __shared__ unsigned char sm[];
    unsigned* tab  = (unsigned*)sm;
    int*      scnt = (int*)(sm + TABSZ * 4);

    const int t = threadIdx.x;
    const int f = blockIdx.x, b = blockIdx.y;
    const float4* col4 = (const float4*)(g_cols + ((size_t)b * FF + f) * SS);

#pragma unroll
    for (int k = 0; k < TABSZ / (256 * 4); k++)
        ((uint4*)tab)[k * 256 + t] = make_uint4(HEMPTY, HEMPTY, HEMPTY, HEMPTY);
    if (t == 0) scnt[0] = 0;

#pragma unroll 1
    for (int half = 0; half < 2; half++) {
        unsigned v[8];
        int p[8];
#pragma unroll
        for (int k = 0; k < 2; k++) {
            const float4 x = __ldg(&col4[half * 512 + k * 256 + t]);
            v[k * 4 + 0] = __float_as_uint(x.x);
            v[k * 4 + 1] = __float_as_uint(x.y);
            v[k * 4 + 2] = __float_as_uint(x.z);
            v[k * 4 + 3] = __float_as_uint(x.w);
        }
#pragma unroll
        for (int k = 0; k < 8; k++) p[k] = hslot(v[k]);
        __syncthreads();                 // table state stable (init or half 0 done)

        if (half == 0) {                 // blind round only on empty table
#pragma unroll
            for (int k = 0; k < 8; k++) tab[p[k]] = v[k];
        }

        unsigned mask = 0xFFu;
        while (__syncthreads_or((int)mask)) {       // prior writes stable
            unsigned wm = 0, pend = mask;
            while (pend) {
                // one 4-slot window step per pending machine; LDS batched 4-wide
#pragma unroll
                for (int c = 0; c < 2; c++) {
                    uint4 g[4];
#pragma unroll
                    for (int j = 0; j < 4; j++) {
                        const int k = c * 4 + j;
                        if (pend & (1u << k))
                            g[j] = *(const uint4*)(tab + (p[k] & ~3));
                    }
#pragma unroll
                    for (int j = 0; j < 4; j++) {
                        const int k = c * 4 + j;
                        if (pend & (1u << k)) {
                            const unsigned sl[4] = {g[j].x, g[j].y, g[j].z, g[j].w};
                            const int base = p[k] & ~3, off = p[k] & 3;
                            int st = -1;
#pragma unroll
                            for (int q = 0; q < 4; q++) {
                                if (st < 0 && q >= off) {
                                    const unsigned u = sl[q];
                                    if (u == v[k]) {
                                        mask &= ~(1u << k); pend &= ~(1u << k); st = q;
                                    } else if (u == HEMPTY) {
                                        wm |= (1u << k); p[k] = base + q;
                                        pend &= ~(1u << k); st = q;
                                    }
                                }
                            }
                            if (st < 0) p[k] = (base + 4) & TABM;
                        }
                    }
                }
            }
            __syncthreads();                        // reads done before writes
#pragma unroll
            for (int k = 0; k < 8; k++)             // writes target EMPTY slots only
                if (wm & (1u << k)) tab[p[k]] = v[k];
        }
    }

    int cnt = 0;
#pragma unroll
    for (int k = 0; k < TABSZ / (256 * 4); k++) {
        const uint4 u = ((const uint4*)tab)[k * 256 + t];
        cnt += (u.x != HEMPTY) + (u.y != HEMPTY) + (u.z != HEMPTY) + (u.w != HEMPTY);
    }
#pragma unroll
    for (int o = 16; o; o >>= 1) cnt += __shfl_xor_sync(0xFFFFFFFFu, cnt, o);
    if ((t & 31) == 0) atomicAdd(&scnt[0], cnt);
    __syncthreads();
    if (t == 0) g_uniq[b * FF + f] = scnt[0];
}

// ---------------------------------------------------------------------------
// Kernel 4: stats assembly + MLP. Grid (32, 16), 256 threads, 16 feat/CTA.
// ---------------------------------------------------------------------------
#define MS_RED  0
#define MS_SST  (MS_RED + 15 * 16 * 4)        // 960
#define MS_H    (MS_SST + 16 * 8 * 4)         // +512
#define MS_W2   (MS_H + 16 * 64 * 4)          // +4096
#define MS_OFF  (MS_W2 + 64 * 128 * 4)        // +32768
#define MSMEM   (MS_OFF + 64)

__global__ void __launch_bounds__(256)
mlp_kernel(const float* __restrict__ w1, const float* __restrict__ b1,
           const float* __restrict__ w2, const float* __restrict__ b2,
           float* __restrict__ out) {
    extern __shared__ unsigned char sm[];
    float* sred  = (float*)(sm + MS_RED);    // [15][16]
    float* sst   = (float*)(sm + MS_SST);    // [16][8]
    float* sh    = (float*)(sm + MS_H);      // [16][64]
    float* sw2   = (float*)(sm + MS_W2);     // [64][128]
    int*   soffs = (int*)(sm + MS_OFF);

    const int t    = threadIdx.x;
    const int tile = blockIdx.x, b = blockIdx.y;

    if (t <= NC) soffs[t] = g_offs[b * (NC + 1) + t];
#pragma unroll
    for (int k = 0; k < 32; k++) sw2[k * 256 + t] = __ldg(&w2[k * 256 + t]);

    if (t < 240) {
        const int qq = t / 16, fl = t & 15;
        sred[qq * 16 + fl] =
            __ldg(&g_fin[((size_t)b * 15 + qq) * FF + tile * 16 + fl]);
    }
    __syncthreads();

    if (t < 16) {
        const int fl = t;
        const float Sf = (float)SS;
        const float sum    = sred[0 * 16 + fl];
        const float sumsq  = sred[1 * 16 + fl];
        const float sumabs = sred[2 * 16 + fl];
        const float mx     = sred[3 * 16 + fl];
        const float nanc   = sred[4 * 16 + fl];
        const float g   = sum / Sf;
        const float var = sumsq / Sf - g * g;
        float between = 0.f;
#pragma unroll
        for (int c = 0; c < NC; c++) {
            const float cntc = (float)(soffs[c + 1] - soffs[c]);
            const float cm = sred[(5 + c) * 16 + fl] / fmaxf(cntc, 1.f);
            const float d = cm - g;
            between += cntc * d * d;
        }
        between /= Sf;
        float st[6];
        st[0] = between / fmaxf(var, 1e-6f);
        st[1] = nanc / Sf;
        st[2] = (float)__ldg(&g_uniq[b * FF + tile * 16 + fl]) / Sf;
        st[3] = var;
        st[4] = sumabs / Sf;
        st[5] = mx;
#pragma unroll
        for (int k = 0; k < 6; k++) {
            float v = st[k];
            if (!isfinite(v)) v = 0.f;
            sst[fl * 8 + k] = v;
        }
    }
    __syncthreads();

    // hidden: 16 x 64 = 1024 over 256 threads
#pragma unroll
    for (int r = 0; r < 4; r++) {
        const int idx = r * 256 + t;
        const int f = idx >> 6, j = idx & 63;
        float z = __ldg(&b1[j]);
#pragma unroll
        for (int i = 0; i < 6; i++) z += sst[f * 8 + i] * __ldg(&w1[i * 64 + j]);
        sh[idx] = z * normcdff(z);           // exact GELU
    }
    __syncthreads();

    // output: 16 x 128 = 2048 over 256 threads
#pragma unroll
    for (int r = 0; r < 8; r++) {
        const int idx = r * 256 + t;
        const int f = idx >> 7, o = idx & 127;
        float z0 = 0.f, z1 = 0.f;
#pragma unroll 16
        for (int j = 0; j < 64; j += 2) {
            z0 += sh[f * 64 + j]     * sw2[j * 128 + o];
            z1 += sh[f * 64 + j + 1] * sw2[(j + 1) * 128 + o];
        }
        out[((size_t)(b * FF) + tile * 16 + f) * 128 + o] =
            z0 + z1 + __ldg(&b2[o]);
    }
}

// ---------------------------------------------------------------------------
extern "C" void kernel_launch(void* const* d_in, const int* in_sizes, int n_in,
                              void* d_out, int out_size) {
    const float* X  = (const float*)d_in[0];
    const int*   y  = (const int*)d_in[1];
    const float* w1 = (const float*)d_in[2];
    const float* b1 = (const float*)d_in[3];
    const float* w2 = (const float*)d_in[4];
    const float* b2 = (const float*)d_in[5];
    float* out = (float*)d_out;

    cudaFuncSetAttribute(stats_kernel,
                         cudaFuncAttributeMaxDynamicSharedMemorySize, SSMEM);
    cudaFuncSetAttribute(stats_kernel,
                         cudaFuncAttributePreferredSharedMemoryCarveout, 100);
    cudaFuncSetAttribute(uniq_kernel,
                         cudaFuncAttributeMaxDynamicSharedMemorySize, USMEM);
    cudaFuncSetAttribute(uniq_kernel,
                         cudaFuncAttributePreferredSharedMemoryCarveout, 100);
    cudaFuncSetAttribute(mlp_kernel,
                         cudaFuncAttributeMaxDynamicSharedMemorySize, MSMEM);

    prep_kernel<<<BB, 256>>>(y);
    stats_kernel<<<dim3(FF / 4, BB), 256, SSMEM>>>(X);
    uniq_kernel<<<dim3(FF, BB), 256, USMEM>>>();
    mlp_kernel<<<dim3(32, BB), 256, MSMEM>>>(w1, b1, w2, b2, out);
}

// round 14
// speedup vs baseline: 1.0262x; 1.0262x over previous
#include <cuda_runtime.h>
#include <math.h>

#define BB 16
#define SS 4096
#define FF 512
#define NC 10
#define TABSZ 8192
#define HEMPTY 0xFFFFFFFFu   // negative-NaN pattern; impossible after canonicalization

// global scratch (static device arrays; no allocation)
__device__ int   g_perm[BB * SS];
__device__ int   g_offs[BB * (NC + 1)];
__device__ float g_fin[BB * 15 * FF];          // [b][q][f]
__device__ int   g_uniq[BB * FF];
__device__ float g_cols[(size_t)BB * FF * SS]; // transposed canonical columns

__device__ __forceinline__ unsigned hslot(unsigned x) {
    x *= 2654435761u;
    return (x >> 19) & (TABSZ - 1);            // 13-bit slot
}

// ---------------------------------------------------------------------------
// Kernel 1: deterministic stable counting sort of y per batch (atomic-free)
// ---------------------------------------------------------------------------
__global__ void prep_kernel(const int* __restrict__ y) {
    __shared__ int histT[NC][256];
    __shared__ int curT[NC][256];
    __shared__ int offs[NC + 1];

    const int b = blockIdx.x;
    const int t = threadIdx.x;
    const int* yb = y + b * SS;
    const int base = t * 16;

#pragma unroll
    for (int c = 0; c < NC; c++) histT[c][t] = 0;
    __syncthreads();
#pragma unroll
    for (int j = 0; j < 16; j++) histT[yb[base + j]][t]++;
    __syncthreads();

    for (int d = 1; d < 256; d <<= 1) {
        int v[NC];
#pragma unroll
        for (int c = 0; c < NC; c++) v[c] = (t >= d) ? histT[c][t - d] : 0;
        __syncthreads();
#pragma unroll
        for (int c = 0; c < NC; c++) histT[c][t] += v[c];
        __syncthreads();
    }

    if (t == 0) {
        offs[0] = 0;
#pragma unroll
        for (int c = 0; c < NC; c++) offs[c + 1] = offs[c] + histT[c][255];
#pragma unroll
        for (int c = 0; c <= NC; c++) g_offs[b * (NC + 1) + c] = offs[c];
    }
    __syncthreads();
#pragma unroll
    for (int c = 0; c < NC; c++)
        curT[c][t] = offs[c] + (t > 0 ? histT[c][t - 1] : 0);
    __syncthreads();
#pragma unroll
    for (int j = 0; j < 16; j++) {
        int s = base + j;
        g_perm[b * SS + curT[yb[s]][t]++] = s;
    }
}

// ---------------------------------------------------------------------------
// Kernel 2: stats kernel — grid (FF/4, BB), 256 threads, 3 CTAs/SM.
// Single X pass: 5 stats + class sums; writes canonical columns to g_cols.
// ---------------------------------------------------------------------------
#define SM_VALS 0
#define SM_RED  65536                    // 20*8 floats
#define SM_OFFS (SM_RED + 640)           // 12 ints
#define SSMEM   (SM_OFFS + 48)

__global__ void __launch_bounds__(256, 3)
stats_kernel(const float* __restrict__ X) {
    extern __shared__ unsigned char sm[];
    float* vals  = (float*)(sm + SM_VALS);
    float* red   = (float*)(sm + SM_RED);
    int*   soffs = (int*)(sm + SM_OFFS);

    const int t  = threadIdx.x;
    const int fg = blockIdx.x, b = blockIdx.y;
    const int lane = t & 31, warp = t >> 5;

    if (t <= NC) soffs[t] = g_offs[b * (NC + 1) + t];

    // ----- Phase 1: load X once (16 independent LDG.128/thread) + 5 stats -----
    const float4* Xb = (const float4*)(X + (size_t)b * SS * FF);
    float s0[4] = {0,0,0,0}, s1[4] = {0,0,0,0}, s2[4] = {0,0,0,0};
    float s3[4] = {0,0,0,0}, s4[4] = {0,0,0,0};

#pragma unroll
    for (int k = 0; k < 16; k++) {
        const int s = k * 256 + t;
        const float4 x = __ldg(&Xb[(size_t)s * (FF / 4) + fg]);
        float xv[4] = {x.x, x.y, x.z, x.w};
#pragma unroll
        for (int f = 0; f < 4; f++) {
            float v = xv[f];
            const bool isn = (v != v);
            v = isn ? 0.f : v;
            v = (v == 0.f) ? 0.f : v;        // -0 -> +0
            const float a = fabsf(v);
            s0[f] += v;
            s1[f] += v * v;
            s2[f] += a;
            s3[f]  = fmaxf(s3[f], a);
            s4[f] += isn ? 1.f : 0.f;
            vals[f * SS + s] = v;
        }
    }

    // reduce 20 class-independent stats
#pragma unroll
    for (int q = 0; q < 20; q++) {
        float v;
        if (q < 4)       v = s0[q];
        else if (q < 8)  v = s1[q - 4];
        else if (q < 12) v = s2[q - 8];
        else if (q < 16) v = s3[q - 12];
        else             v = s4[q - 16];
        const bool ismax = (q >= 12 && q < 16);
#pragma unroll
        for (int o = 16; o; o >>= 1) {
            float w = __shfl_xor_sync(0xFFFFFFFFu, v, o);
            v = ismax ? fmaxf(v, w) : (v + w);
        }
        if (lane == 0) red[q * 8 + warp] = v;
    }
    __syncthreads();
    if (t < 20) {
        const bool ismax = ((t >> 2) == 3);
        float v = red[t * 8];
#pragma unroll
        for (int w = 1; w < 8; w++)
            v = ismax ? fmaxf(v, red[t * 8 + w]) : (v + red[t * 8 + w]);
        g_fin[((size_t)b * 15 + (t >> 2)) * FF + fg * 4 + (t & 3)] = v;
    }

    // ----- Phase 2: write transposed canonical columns (coalesced) -----
#pragma unroll
    for (int f = 0; f < 4; f++) {
        float4*       dst = (float4*)(g_cols + ((size_t)b * FF + fg * 4 + f) * SS);
        const float4* src = (const float4*)(vals + f * SS);
#pragma unroll
        for (int k = 0; k < 4; k++) dst[k * 256 + t] = src[k * 256 + t];
    }

    // ----- Phase 3: per-class sums from smem in perm order (2 groups of 5) -----
    const int* perm = g_perm + b * SS;
#pragma unroll 1
    for (int grp = 0; grp < 2; grp++) {
        float cls[5][4];
#pragma unroll
        for (int c = 0; c < 5; c++)
#pragma unroll
            for (int f = 0; f < 4; f++) cls[c][f] = 0.f;

#pragma unroll
        for (int c = 0; c < 5; c++) {
            const int cc = grp * 5 + c;
            const int lo = soffs[cc], hi = soffs[cc + 1];
            for (int i = lo + t; i < hi; i += 256) {
                const int s = __ldg(&perm[i]);
#pragma unroll
                for (int f = 0; f < 4; f++) cls[c][f] += vals[f * SS + s];
            }
        }
#pragma unroll
        for (int q = 0; q < 20; q++) {
            float v = cls[q >> 2][q & 3];
#pragma unroll
            for (int o = 16; o; o >>= 1)
                v += __shfl_xor_sync(0xFFFFFFFFu, v, o);
            if (lane == 0) red[q * 8 + warp] = v;
        }
        __syncthreads();
        if (t < 20) {
            float v = red[t * 8];
#pragma unroll
            for (int w = 1; w < 8; w++) v += red[t * 8 + w];
            const int c = grp * 5 + (t >> 2);
            g_fin[((size_t)b * 15 + 5 + c) * FF + fg * 4 + (t & 3)] = v;
        }
        __syncthreads();
    }
}

// ---------------------------------------------------------------------------
// Kernel 3: uniq kernel — one CTA per (f, b), 256 threads, 33KB smem.
// WARP-SLICED hash: warp w owns slots [w*1024, w*1024+1024). Each warp scans
// the full column (L1-cached, coalesced) and inserts only values whose hash
// falls in its slice, using __syncwarp-round blind-write + verify. No
// cross-warp races (slice-private) -> exact deterministic count.
// ---------------------------------------------------------------------------
#define USMEM (TABSZ * 4 + 16)

__global__ void __launch_bounds__(256, 5)
uniq_kernel() {
    extern __shared__ unsigned char sm[];
    unsigned* tab  = (unsigned*)sm;
    int*      scnt = (int*)(sm + TABSZ * 4);

    const int t = threadIdx.x, lane = t & 31, w = t >> 5;
    const int f = blockIdx.x, b = blockIdx.y;
    const uint4* col4 = (const uint4*)(g_cols + ((size_t)b * FF + f) * SS);
    const unsigned sliceBase = (unsigned)w << 10;

#pragma unroll
    for (int k = 0; k < TABSZ / 256; k++) tab[k * 256 + t] = HEMPTY;
    if (t == 0) scnt[0] = 0;
    __syncthreads();

    // 16 chunks of 256 values; each lane takes 2 float4 (8 values) per chunk
#pragma unroll 1
    for (int chunk = 0; chunk < 16; chunk++) {
        unsigned v[8];
        unsigned p[8];
        unsigned act = 0;
#pragma unroll
        for (int k2 = 0; k2 < 2; k2++) {
            const uint4 q = __ldg(&col4[chunk * 64 + k2 * 32 + lane]);
            const unsigned vv[4] = {q.x, q.y, q.z, q.w};
#pragma unroll
            for (int j = 0; j < 4; j++) {
                const int k = k2 * 4 + j;
                const unsigned hv = hslot(vv[j]);
                v[k] = vv[j];
                p[k] = hv;
                if ((int)(hv >> 10) == w) act |= 1u << k;
            }
        }

        while (__any_sync(0xFFFFFFFFu, (int)act)) {
            unsigned wm = 0;
#pragma unroll
            for (int k = 0; k < 8; k++) {
                if (act & (1u << k)) {
                    unsigned pp = p[k];
                    for (;;) {                       // scan warp-stable snapshot
                        const unsigned u = tab[pp];
                        if (u == v[k]) { act &= ~(1u << k); break; }
                        if (u == HEMPTY) { wm |= 1u << k; break; }
                        pp = sliceBase | ((pp + 1) & 1023);
                    }
                    p[k] = pp;
                }
            }
            __syncwarp();                            // reads done
#pragma unroll
            for (int k = 0; k < 8; k++)              // write only to slots read EMPTY
                if (wm & (1u << k)) tab[p[k]] = v[k];
            __syncwarp();                            // writes stable for next round
        }
    }
    __syncthreads();

    int cnt = 0;
#pragma unroll
    for (int k = 0; k < TABSZ / (256 * 4); k++) {
        const uint4 u = ((const uint4*)tab)[k * 256 + t];
        cnt += (u.x != HEMPTY) + (u.y != HEMPTY) + (u.z != HEMPTY) + (u.w != HEMPTY);
    }
#pragma unroll
    for (int o = 16; o; o >>= 1) cnt += __shfl_xor_sync(0xFFFFFFFFu, cnt, o);
    if (lane == 0) atomicAdd(&scnt[0], cnt);
    __syncthreads();
    if (t == 0) g_uniq[b * FF + f] = scnt[0];
}

// ---------------------------------------------------------------------------
// Kernel 4: stats assembly + MLP. Grid (32, 16), 256 threads, 16 feat/CTA.
// ---------------------------------------------------------------------------
#define MS_RED  0
#define MS_SST  (MS_RED + 15 * 16 * 4)        // 960
#define MS_H    (MS_SST + 16 * 8 * 4)         // +512
#define MS_W2   (MS_H + 16 * 64 * 4)          // +4096
#define MS_OFF  (MS_W2 + 64 * 128 * 4)        // +32768
#define MSMEM   (MS_OFF + 64)

__global__ void __launch_bounds__(256)
mlp_kernel(const float* __restrict__ w1, const float* __restrict__ b1,
           const float* __restrict__ w2, const float* __restrict__ b2,
           float* __restrict__ out) {
    extern __shared__ unsigned char sm[];
    float* sred  = (float*)(sm + MS_RED);    // [15][16]
    float* sst   = (float*)(sm + MS_SST);    // [16][8]
    float* sh    = (float*)(sm + MS_H);      // [16][64]
    float* sw2   = (float*)(sm + MS_W2);     // [64][128]
    int*   soffs = (int*)(sm + MS_OFF);

    const int t    = threadIdx.x;
    const int tile = blockIdx.x, b = blockIdx.y;

    if (t <= NC) soffs[t] = g_offs[b * (NC + 1) + t];
#pragma unroll
    for (int k = 0; k < 32; k++) sw2[k * 256 + t] = __ldg(&w2[k * 256 + t]);

    if (t < 240) {
        const int qq = t / 16, fl = t & 15;
        sred[qq * 16 + fl] =
            __ldg(&g_fin[((size_t)b * 15 + qq) * FF + tile * 16 + fl]);
    }
    __syncthreads();

    if (t < 16) {
        const int fl = t;
        const float Sf = (float)SS;
        const float sum    = sred[0 * 16 + fl];
        const float sumsq  = sred[1 * 16 + fl];
        const float sumabs = sred[2 * 16 + fl];
        const float mx     = sred[3 * 16 + fl];
        const float nanc   = sred[4 * 16 + fl];
        const float g   = sum / Sf;
        const float var = sumsq / Sf - g * g;
        float between = 0.f;
#pragma unroll
        for (int c = 0; c < NC; c++) {
            const float cntc = (float)(soffs[c + 1] - soffs[c]);
            const float cm = sred[(5 + c) * 16 + fl] / fmaxf(cntc, 1.f);
            const float d = cm - g;
            between += cntc * d * d;
        }
        between /= Sf;
        float st[6];
        st[0] = between / fmaxf(var, 1e-6f);
        st[1] = nanc / Sf;
        st[2] = (float)__ldg(&g_uniq[b * FF + tile * 16 + fl]) / Sf;
        st[3] = var;
        st[4] = sumabs / Sf;
        st[5] = mx;
#pragma unroll
        for (int k = 0; k < 6; k++) {
            float v = st[k];
            if (!isfinite(v)) v = 0.f;
            sst[fl * 8 + k] = v;
        }
    }
    __syncthreads();

    // hidden: 16 x 64 = 1024 over 256 threads
#pragma unroll
    for (int r = 0; r < 4; r++) {
        const int idx = r * 256 + t;
        const int f = idx >> 6, j = idx & 63;
        float z = __ldg(&b1[j]);
#pragma unroll
        for (int i = 0; i < 6; i++) z += sst[f * 8 + i] * __ldg(&w1[i * 64 + j]);
        sh[idx] = z * normcdff(z);           // exact GELU
    }
    __syncthreads();

    // output: 16 x 128 = 2048 over 256 threads
#pragma unroll
    for (int r = 0; r < 8; r++) {
        const int idx = r * 256 + t;
        const int f = idx >> 7, o = idx & 127;
        float z0 = 0.f, z1 = 0.f;
#pragma unroll 16
        for (int j = 0; j < 64; j += 2) {
            z0 += sh[f * 64 + j]     * sw2[j * 128 + o];
            z1 += sh[f * 64 + j + 1] * sw2[(j + 1) * 128 + o];
        }
        out[((size_t)(b * FF) + tile * 16 + f) * 128 + o] =
            z0 + z1 + __ldg(&b2[o]);
    }
}

// ---------------------------------------------------------------------------
extern "C" void kernel_launch(void* const* d_in, const int* in_sizes, int n_in,
                              void* d_out, int out_size) {
    const float* X  = (const float*)d_in[0];
    const int*   y  = (const int*)d_in[1];
    const float* w1 = (const float*)d_in[2];
    const float* b1 = (const float*)d_in[3];
    const float* w2 = (const float*)d_in[4];
    const float* b2 = (const float*)d_in[5];
    float* out = (float*)d_out;

    cudaFuncSetAttribute(stats_kernel,
                         cudaFuncAttributeMaxDynamicSharedMemorySize, SSMEM);
    cudaFuncSetAttribute(stats_kernel,
                         cudaFuncAttributePreferredSharedMemoryCarveout, 100);
    cudaFuncSetAttribute(uniq_kernel,
                         cudaFuncAttributeMaxDynamicSharedMemorySize, USMEM);
    cudaFuncSetAttribute(uniq_kernel,
                         cudaFuncAttributePreferredSharedMemoryCarveout, 100);
    cudaFuncSetAttribute(mlp_kernel,
                         cudaFuncAttributeMaxDynamicSharedMemorySize, MSMEM);

    prep_kernel<<<BB, 256>>>(y);
    stats_kernel<<<dim3(FF / 4, BB), 256, SSMEM>>>(X);
    uniq_kernel<<<dim3(FF, BB), 256, USMEM>>>();
    mlp_kernel<<<dim3(32, BB), 256, MSMEM>>>(w1, b1, w2, b2, out);
}

// round 15
// speedup vs baseline: 1.6357x; 1.5939x over previous
#include <cuda_runtime.h>
#include <math.h>

#define BB 16
#define SS 4096
#define FF 512
#define NC 10
#define TABSZ 8192
#define TABM  8191
#define HEMPTY 0xFFFFFFFFu   // negative-NaN pattern; impossible after canonicalization

// global scratch (static device arrays; no allocation)
__device__ int   g_perm[BB * SS];
__device__ int   g_offs[BB * (NC + 1)];
__device__ float g_fin[BB * 15 * FF];          // [b][q][f]
__device__ int   g_uniq[BB * FF];
__device__ float g_cols[(size_t)BB * FF * SS]; // transposed canonical columns

__device__ __forceinline__ unsigned hslot(unsigned x) {
    x *= 2654435761u;
    return (x >> 19) & TABM;
}
// second hash: odd step -> full cycle over power-of-2 table
__device__ __forceinline__ unsigned hstep(unsigned x) {
    x *= 0x9E3779B1u;
    return ((x >> 16) | 1u) & TABM;
}

// ---------------------------------------------------------------------------
// Kernel 1: deterministic stable counting sort of y per batch (atomic-free)
// ---------------------------------------------------------------------------
__global__ void prep_kernel(const int* __restrict__ y) {
    __shared__ int histT[NC][256];
    __shared__ int curT[NC][256];
    __shared__ int offs[NC + 1];

    const int b = blockIdx.x;
    const int t = threadIdx.x;
    const int* yb = y + b * SS;
    const int base = t * 16;

#pragma unroll
    for (int c = 0; c < NC; c++) histT[c][t] = 0;
    __syncthreads();
#pragma unroll
    for (int j = 0; j < 16; j++) histT[yb[base + j]][t]++;
    __syncthreads();

    for (int d = 1; d < 256; d <<= 1) {
        int v[NC];
#pragma unroll
        for (int c = 0; c < NC; c++) v[c] = (t >= d) ? histT[c][t - d] : 0;
        __syncthreads();
#pragma unroll
        for (int c = 0; c < NC; c++) histT[c][t] += v[c];
        __syncthreads();
    }

    if (t == 0) {
        offs[0] = 0;
#pragma unroll
        for (int c = 0; c < NC; c++) offs[c + 1] = offs[c] + histT[c][255];
#pragma unroll
        for (int c = 0; c <= NC; c++) g_offs[b * (NC + 1) + c] = offs[c];
    }
    __syncthreads();
#pragma unroll
    for (int c = 0; c < NC; c++)
        curT[c][t] = offs[c] + (t > 0 ? histT[c][t - 1] : 0);
    __syncthreads();
#pragma unroll
    for (int j = 0; j < 16; j++) {
        int s = base + j;
        g_perm[b * SS + curT[yb[s]][t]++] = s;
    }
}

// ---------------------------------------------------------------------------
// Kernel 2: stats kernel — grid (FF/4, BB), 256 threads, 3 CTAs/SM.
// Single X pass: 5 stats + class sums; writes canonical columns to g_cols.
// ---------------------------------------------------------------------------
#define SM_VALS 0
#define SM_RED  65536                    // 20*8 floats
#define SM_OFFS (SM_RED + 640)           // 12 ints
#define SSMEM   (SM_OFFS + 48)

__global__ void __launch_bounds__(256, 3)
stats_kernel(const float* __restrict__ X) {
    extern __shared__ unsigned char sm[];
    float* vals  = (float*)(sm + SM_VALS);
    float* red   = (float*)(sm + SM_RED);
    int*   soffs = (int*)(sm + SM_OFFS);

    const int t  = threadIdx.x;
    const int fg = blockIdx.x, b = blockIdx.y;
    const int lane = t & 31, warp = t >> 5;

    if (t <= NC) soffs[t] = g_offs[b * (NC + 1) + t];

    // ----- Phase 1: load X once (16 independent LDG.128/thread) + 5 stats -----
    const float4* Xb = (const float4*)(X + (size_t)b * SS * FF);
    float s0[4] = {0,0,0,0}, s1[4] = {0,0,0,0}, s2[4] = {0,0,0,0};
    float s3[4] = {0,0,0,0}, s4[4] = {0,0,0,0};

#pragma unroll
    for (int k = 0; k < 16; k++) {
        const int s = k * 256 + t;
        const float4 x = __ldg(&Xb[(size_t)s * (FF / 4) + fg]);
        float xv[4] = {x.x, x.y, x.z, x.w};
#pragma unroll
        for (int f = 0; f < 4; f++) {
            float v = xv[f];
            const bool isn = (v != v);
            v = isn ? 0.f : v;
            v = (v == 0.f) ? 0.f : v;        // -0 -> +0
            const float a = fabsf(v);
            s0[f] += v;
            s1[f] += v * v;
            s2[f] += a;
            s3[f]  = fmaxf(s3[f], a);
            s4[f] += isn ? 1.f : 0.f;
            vals[f * SS + s] = v;
        }
    }

    // reduce 20 class-independent stats
#pragma unroll
    for (int q = 0; q < 20; q++) {
        float v;
        if (q < 4)       v = s0[q];
        else if (q < 8)  v = s1[q - 4];
        else if (q < 12) v = s2[q - 8];
        else if (q < 16) v = s3[q - 12];
        else             v = s4[q - 16];
        const bool ismax = (q >= 12 && q < 16);
#pragma unroll
        for (int o = 16; o; o >>= 1) {
            float w = __shfl_xor_sync(0xFFFFFFFFu, v, o);
            v = ismax ? fmaxf(v, w) : (v + w);
        }
        if (lane == 0) red[q * 8 + warp] = v;
    }
    __syncthreads();
    if (t < 20) {
        const bool ismax = ((t >> 2) == 3);
        float v = red[t * 8];
#pragma unroll
        for (int w = 1; w < 8; w++)
            v = ismax ? fmaxf(v, red[t * 8 + w]) : (v + red[t * 8 + w]);
        g_fin[((size_t)b * 15 + (t >> 2)) * FF + fg * 4 + (t & 3)] = v;
    }

    // ----- Phase 2: write transposed canonical columns (coalesced) -----
#pragma unroll
    for (int f = 0; f < 4; f++) {
        float4*       dst = (float4*)(g_cols + ((size_t)b * FF + fg * 4 + f) * SS);
        const float4* src = (const float4*)(vals + f * SS);
#pragma unroll
        for (int k = 0; k < 4; k++) dst[k * 256 + t] = src[k * 256 + t];
    }

    // ----- Phase 3: per-class sums from smem in perm order (2 groups of 5) -----
    const int* perm = g_perm + b * SS;
#pragma unroll 1
    for (int grp = 0; grp < 2; grp++) {
        float cls[5][4];
#pragma unroll
        for (int c = 0; c < 5; c++)
#pragma unroll
            for (int f = 0; f < 4; f++) cls[c][f] = 0.f;

#pragma unroll
        for (int c = 0; c < 5; c++) {
            const int cc = grp * 5 + c;
            const int lo = soffs[cc], hi = soffs[cc + 1];
            for (int i = lo + t; i < hi; i += 256) {
                const int s = __ldg(&perm[i]);
#pragma unroll
                for (int f = 0; f < 4; f++) cls[c][f] += vals[f * SS + s];
            }
        }
#pragma unroll
        for (int q = 0; q < 20; q++) {
            float v = cls[q >> 2][q & 3];
#pragma unroll
            for (int o = 16; o; o >>= 1)
                v += __shfl_xor_sync(0xFFFFFFFFu, v, o);
            if (lane == 0) red[q * 8 + warp] = v;
        }
        __syncthreads();
        if (t < 20) {
            float v = red[t * 8];
#pragma unroll
            for (int w = 1; w < 8; w++) v += red[t * 8 + w];
            const int c = grp * 5 + (t >> 2);
            g_fin[((size_t)b * 15 + 5 + c) * FF + fg * 4 + (t & 3)] = v;
        }
        __syncthreads();
    }
}

// ---------------------------------------------------------------------------
// Kernel 3: uniq kernel — one CTA per (f, b), 256 threads, 33KB smem,
// 6 CTAs/SM. Two insert halves; BREADTH-FIRST verify with DOUBLE HASHING.
// Round invariant: table stable at round start; reads complete before the
// round's writes; writes target only slots read EMPTY this round. Identical
// values share identical probe sequences -> exact deterministic count.
// ---------------------------------------------------------------------------
#define USMEM (TABSZ * 4 + 16)

__global__ void __launch_bounds__(256, 6)
uniq_kernel() {
    extern __shared__ unsigned char sm[];
    unsigned* tab  = (unsigned*)sm;
    int*      scnt = (int*)(sm + TABSZ * 4);

    const int t = threadIdx.x;
    const int f = blockIdx.x, b = blockIdx.y;
    const float4* col4 = (const float4*)(g_cols + ((size_t)b * FF + f) * SS);

#pragma unroll
    for (int k = 0; k < TABSZ / (256 * 4); k++)
        ((uint4*)tab)[k * 256 + t] = make_uint4(HEMPTY, HEMPTY, HEMPTY, HEMPTY);
    if (t == 0) scnt[0] = 0;

#pragma unroll 1
    for (int half = 0; half < 2; half++) {
        unsigned v[8];
        unsigned p[8];
#pragma unroll
        for (int k = 0; k < 2; k++) {
            const float4 x = __ldg(&col4[half * 512 + k * 256 + t]);
            v[k * 4 + 0] = __float_as_uint(x.x);
            v[k * 4 + 1] = __float_as_uint(x.y);
            v[k * 4 + 2] = __float_as_uint(x.z);
            v[k * 4 + 3] = __float_as_uint(x.w);
        }
#pragma unroll
        for (int k = 0; k < 8; k++) p[k] = hslot(v[k]);
        __syncthreads();                 // table state stable (init or half 0 done)

        if (half == 0) {                 // blind round only on empty table
#pragma unroll
            for (int k = 0; k < 8; k++) tab[p[k]] = v[k];
        }

        unsigned mask = 0xFFu;
        while (__syncthreads_or((int)mask)) {     // prior writes stable
            unsigned wm = 0, pend = mask;
            while (pend) {
                // breadth-first: batch independent LDS for all pending machines
                unsigned u[8];
#pragma unroll
                for (int k = 0; k < 8; k++)
                    if (pend & (1u << k)) u[k] = tab[p[k]];
#pragma unroll
                for (int k = 0; k < 8; k++) {
                    if (pend & (1u << k)) {
                        if (u[k] == v[k]) {
                            mask &= ~(1u << k); pend &= ~(1u << k);
                        } else if (u[k] == HEMPTY) {
                            wm |= (1u << k);   pend &= ~(1u << k);
                        } else {
                            p[k] = (p[k] + hstep(v[k])) & TABM;  // double hash
                        }
                    }
                }
            }
            __syncthreads();                      // reads done before writes
#pragma unroll
            for (int k = 0; k < 8; k++)           // writes target EMPTY slots only
                if (wm & (1u << k)) tab[p[k]] = v[k];
        }
    }

    int cnt = 0;
#pragma unroll
    for (int k = 0; k < TABSZ / (256 * 4); k++) {
        const uint4 u = ((const uint4*)tab)[k * 256 + t];
        cnt += (u.x != HEMPTY) + (u.y != HEMPTY) + (u.z != HEMPTY) + (u.w != HEMPTY);
    }
#pragma unroll
    for (int o = 16; o; o >>= 1) cnt += __shfl_xor_sync(0xFFFFFFFFu, cnt, o);
    if ((t & 31) == 0) atomicAdd(&scnt[0], cnt);
    __syncthreads();
    if (t == 0) g_uniq[b * FF + f] = scnt[0];
}

// ---------------------------------------------------------------------------
// Kernel 4: stats assembly + MLP. Grid (32, 16), 256 threads, 16 feat/CTA.
// ---------------------------------------------------------------------------
#define MS_RED  0
#define MS_SST  (MS_RED + 15 * 16 * 4)        // 960
#define MS_H    (MS_SST + 16 * 8 * 4)         // +512
#define MS_W2   (MS_H + 16 * 64 * 4)          // +4096
#define MS_OFF  (MS_W2 + 64 * 128 * 4)        // +32768
#define MSMEM   (MS_OFF + 64)

__global__ void __launch_bounds__(256)
mlp_kernel(const float* __restrict__ w1, const float* __restrict__ b1,
           const float* __restrict__ w2, const float* __restrict__ b2,
           float* __restrict__ out) {
    extern __shared__ unsigned char sm[];
    float* sred  = (float*)(sm + MS_RED);    // [15][16]
    float* sst   = (float*)(sm + MS_SST);    // [16][8]
    float* sh    = (float*)(sm + MS_H);      // [16][64]
    float* sw2   = (float*)(sm + MS_W2);     // [64][128]
    int*   soffs = (int*)(sm + MS_OFF);

    const int t    = threadIdx.x;
    const int tile = blockIdx.x, b = blockIdx.y;

    if (t <= NC) soffs[t] = g_offs[b * (NC + 1) + t];
#pragma unroll
    for (int k = 0; k < 32; k++) sw2[k * 256 + t] = __ldg(&w2[k * 256 + t]);

    if (t < 240) {
        const int qq = t / 16, fl = t & 15;
        sred[qq * 16 + fl] =
            __ldg(&g_fin[((size_t)b * 15 + qq) * FF + tile * 16 + fl]);
    }
    __syncthreads();

    if (t < 16) {
        const int fl = t;
        const float Sf = (float)SS;
        const float sum    = sred[0 * 16 + fl];
        const float sumsq  = sred[1 * 16 + fl];
        const float sumabs = sred[2 * 16 + fl];
        const float mx     = sred[3 * 16 + fl];
        const float nanc   = sred[4 * 16 + fl];
        const float g   = sum / Sf;
        const float var = sumsq / Sf - g * g;
        float between = 0.f;
#pragma unroll
        for (int c = 0; c < NC; c++) {
            const float cntc = (float)(soffs[c + 1] - soffs[c]);
            const float cm = sred[(5 + c) * 16 + fl] / fmaxf(cntc, 1.f);
            const float d = cm - g;
            between += cntc * d * d;
        }
        between /= Sf;
        float st[6];
        st[0] = between / fmaxf(var, 1e-6f);
        st[1] = nanc / Sf;
        st[2] = (float)__ldg(&g_uniq[b * FF + tile * 16 + fl]) / Sf;
        st[3] = var;
        st[4] = sumabs / Sf;
        st[5] = mx;
#pragma unroll
        for (int k = 0; k < 6; k++) {
            float v = st[k];
            if (!isfinite(v)) v = 0.f;
            sst[fl * 8 + k] = v;
        }
    }
    __syncthreads();

    // hidden: 16 x 64 = 1024 over 256 threads
#pragma unroll
    for (int r = 0; r < 4; r++) {
        const int idx = r * 256 + t;
        const int f = idx >> 6, j = idx & 63;
        float z = __ldg(&b1[j]);
#pragma unroll
        for (int i = 0; i < 6; i++) z += sst[f * 8 + i] * __ldg(&w1[i * 64 + j]);
        sh[idx] = z * normcdff(z);           // exact GELU
    }
    __syncthreads();

    // output: 16 x 128 = 2048 over 256 threads
#pragma unroll
    for (int r = 0; r < 8; r++) {
        const int idx = r * 256 + t;
        const int f = idx >> 7, o = idx & 127;
        float z0 = 0.f, z1 = 0.f;
#pragma unroll 16
        for (int j = 0; j < 64; j += 2) {
            z0 += sh[f * 64 + j]     * sw2[j * 128 + o];
            z1 += sh[f * 64 + j + 1] * sw2[(j + 1) * 128 + o];
        }
        out[((size_t)(b * FF) + tile * 16 + f) * 128 + o] =
            z0 + z1 + __ldg(&b2[o]);
    }
}

// ---------------------------------------------------------------------------
extern "C" void kernel_launch(void* const* d_in, const int* in_sizes, int n_in,
                              void* d_out, int out_size) {
    const float* X  = (const float*)d_in[0];
    const int*   y  = (const int*)d_in[1];
    const float* w1 = (const float*)d_in[2];
    const float* b1 = (const float*)d_in[3];
    const float* w2 = (const float*)d_in[4];
    const float* b2 = (const float*)d_in[5];
    float* out = (float*)d_out;

    cudaFuncSetAttribute(stats_kernel,
                         cudaFuncAttributeMaxDynamicSharedMemorySize, SSMEM);
    cudaFuncSetAttribute(stats_kernel,
                         cudaFuncAttributePreferredSharedMemoryCarveout, 100);
    cudaFuncSetAttribute(uniq_kernel,
                         cudaFuncAttributeMaxDynamicSharedMemorySize, USMEM);
    cudaFuncSetAttribute(uniq_kernel,
                         cudaFuncAttributePreferredSharedMemoryCarveout, 100);
    cudaFuncSetAttribute(mlp_kernel,
                         cudaFuncAttributeMaxDynamicSharedMemorySize, MSMEM);

    prep_kernel<<<BB, 256>>>(y);
    stats_kernel<<<dim3(FF / 4, BB), 256, SSMEM>>>(X);
    uniq_kernel<<<dim3(FF, BB), 256, USMEM>>>();
    mlp_kernel<<<dim3(32, BB), 256, MSMEM>>>(w1, b1, w2, b2, out);
}

// round 16
// speedup vs baseline: 2.0577x; 1.2580x over previous
#include <cuda_runtime.h>
#include <math.h>

#define BB 16
#define SS 4096
#define FF 512
#define NC 10
#define TABSZ 8192
#define TABM  8191
#define HEMPTY 0xFFFFFFFFu   // negative-NaN pattern; impossible after canonicalization

// global scratch (static device arrays; no allocation)
__device__ int   g_perm[BB * SS];
__device__ int   g_offs[BB * (NC + 1)];
__device__ float g_fin[BB * 15 * FF];          // [b][q][f]
__device__ int   g_uniq[BB * FF];
__device__ float g_cols[(size_t)BB * FF * SS]; // transposed canonical columns

__device__ __forceinline__ unsigned hslot(unsigned x) {
    x *= 2654435761u;
    return (x >> 19) & TABM;
}
// second hash: odd step -> full cycle over power-of-2 table (kills clustering)
__device__ __forceinline__ unsigned hstep(unsigned x) {
    x *= 0x9E3779B1u;
    return ((x >> 16) | 1u) & TABM;
}

// ---------------------------------------------------------------------------
// Kernel 1: deterministic stable counting sort of y per batch (atomic-free)
// ---------------------------------------------------------------------------
__global__ void prep_kernel(const int* __restrict__ y) {
    __shared__ int histT[NC][256];
    __shared__ int curT[NC][256];
    __shared__ int offs[NC + 1];

    const int b = blockIdx.x;
    const int t = threadIdx.x;
    const int* yb = y + b * SS;
    const int base = t * 16;

#pragma unroll
    for (int c = 0; c < NC; c++) histT[c][t] = 0;
    __syncthreads();
#pragma unroll
    for (int j = 0; j < 16; j++) histT[yb[base + j]][t]++;
    __syncthreads();

    for (int d = 1; d < 256; d <<= 1) {
        int v[NC];
#pragma unroll
        for (int c = 0; c < NC; c++) v[c] = (t >= d) ? histT[c][t - d] : 0;
        __syncthreads();
#pragma unroll
        for (int c = 0; c < NC; c++) histT[c][t] += v[c];
        __syncthreads();
    }

    if (t == 0) {
        offs[0] = 0;
#pragma unroll
        for (int c = 0; c < NC; c++) offs[c + 1] = offs[c] + histT[c][255];
#pragma unroll
        for (int c = 0; c <= NC; c++) g_offs[b * (NC + 1) + c] = offs[c];
    }
    __syncthreads();
#pragma unroll
    for (int c = 0; c < NC; c++)
        curT[c][t] = offs[c] + (t > 0 ? histT[c][t - 1] : 0);
    __syncthreads();
#pragma unroll
    for (int j = 0; j < 16; j++) {
        int s = base + j;
        g_perm[b * SS + curT[yb[s]][t]++] = s;
    }
}

// ---------------------------------------------------------------------------
// Kernel 2: stats kernel — grid (FF/4, BB), 256 threads, 3 CTAs/SM.
// Single X pass: 5 stats + class sums; writes canonical columns to g_cols.
// ---------------------------------------------------------------------------
#define SM_VALS 0
#define SM_RED  65536                    // 20*8 floats
#define SM_OFFS (SM_RED + 640)           // 12 ints
#define SSMEM   (SM_OFFS + 48)

__global__ void __launch_bounds__(256, 3)
stats_kernel(const float* __restrict__ X) {
    extern __shared__ unsigned char sm[];
    float* vals  = (float*)(sm + SM_VALS);
    float* red   = (float*)(sm + SM_RED);
    int*   soffs = (int*)(sm + SM_OFFS);

    const int t  = threadIdx.x;
    const int fg = blockIdx.x, b = blockIdx.y;
    const int lane = t & 31, warp = t >> 5;

    if (t <= NC) soffs[t] = g_offs[b * (NC + 1) + t];

    // ----- Phase 1: load X once (16 independent LDG.128/thread) + 5 stats -----
    const float4* Xb = (const float4*)(X + (size_t)b * SS * FF);
    float s0[4] = {0,0,0,0}, s1[4] = {0,0,0,0}, s2[4] = {0,0,0,0};
    float s3[4] = {0,0,0,0}, s4[4] = {0,0,0,0};

#pragma unroll
    for (int k = 0; k < 16; k++) {
        const int s = k * 256 + t;
        const float4 x = __ldg(&Xb[(size_t)s * (FF / 4) + fg]);
        float xv[4] = {x.x, x.y, x.z, x.w};
#pragma unroll
        for (int f = 0; f < 4; f++) {
            float v = xv[f];
            const bool isn = (v != v);
            v = isn ? 0.f : v;
            v = (v == 0.f) ? 0.f : v;        // -0 -> +0
            const float a = fabsf(v);
            s0[f] += v;
            s1[f] += v * v;
            s2[f] += a;
            s3[f]  = fmaxf(s3[f], a);
            s4[f] += isn ? 1.f : 0.f;
            vals[f * SS + s] = v;
        }
    }

    // reduce 20 class-independent stats
#pragma unroll
    for (int q = 0; q < 20; q++) {
        float v;
        if (q < 4)       v = s0[q];
        else if (q < 8)  v = s1[q - 4];
        else if (q < 12) v = s2[q - 8];
        else if (q < 16) v = s3[q - 12];
        else             v = s4[q - 16];
        const bool ismax = (q >= 12 && q < 16);
#pragma unroll
        for (int o = 16; o; o >>= 1) {
            float w = __shfl_xor_sync(0xFFFFFFFFu, v, o);
            v = ismax ? fmaxf(v, w) : (v + w);
        }
        if (lane == 0) red[q * 8 + warp] = v;
    }
    __syncthreads();
    if (t < 20) {
        const bool ismax = ((t >> 2) == 3);
        float v = red[t * 8];
#pragma unroll
        for (int w = 1; w < 8; w++)
            v = ismax ? fmaxf(v, red[t * 8 + w]) : (v + red[t * 8 + w]);
        g_fin[((size_t)b * 15 + (t >> 2)) * FF + fg * 4 + (t & 3)] = v;
    }

    // ----- Phase 2: write transposed canonical columns (coalesced) -----
#pragma unroll
    for (int f = 0; f < 4; f++) {
        float4*       dst = (float4*)(g_cols + ((size_t)b * FF + fg * 4 + f) * SS);
        const float4* src = (const float4*)(vals + f * SS);
#pragma unroll
        for (int k = 0; k < 4; k++) dst[k * 256 + t] = src[k * 256 + t];
    }

    // ----- Phase 3: per-class sums from smem in perm order (2 groups of 5) -----
    const int* perm = g_perm + b * SS;
#pragma unroll 1
    for (int grp = 0; grp < 2; grp++) {
        float cls[5][4];
#pragma unroll
        for (int c = 0; c < 5; c++)
#pragma unroll
            for (int f = 0; f < 4; f++) cls[c][f] = 0.f;

#pragma unroll
        for (int c = 0; c < 5; c++) {
            const int cc = grp * 5 + c;
            const int lo = soffs[cc], hi = soffs[cc + 1];
            for (int i = lo + t; i < hi; i += 256) {
                const int s = __ldg(&perm[i]);
#pragma unroll
                for (int f = 0; f < 4; f++) cls[c][f] += vals[f * SS + s];
            }
        }
#pragma unroll
        for (int q = 0; q < 20; q++) {
            float v = cls[q >> 2][q & 3];
#pragma unroll
            for (int o = 16; o; o >>= 1)
                v += __shfl_xor_sync(0xFFFFFFFFu, v, o);
            if (lane == 0) red[q * 8 + warp] = v;
        }
        __syncthreads();
        if (t < 20) {
            float v = red[t * 8];
#pragma unroll
            for (int w = 1; w < 8; w++) v += red[t * 8 + w];
            const int c = grp * 5 + (t >> 2);
            g_fin[((size_t)b * 15 + 5 + c) * FF + fg * 4 + (t & 3)] = v;
        }
        __syncthreads();
    }
}

// ---------------------------------------------------------------------------
// Kernel 3: uniq kernel — one CTA per (f, b), 256 threads, 33KB smem,
// 6 CTAs/SM. Two insert halves; serial verify-scan with DOUBLE HASHING
// (only change vs the 350us baseline: probe step +1 -> +hstep(v)).
// ---------------------------------------------------------------------------
#define USMEM (TABSZ * 4 + 16)

__global__ void __launch_bounds__(256, 6)
uniq_kernel() {
    extern __shared__ unsigned char sm[];
    unsigned* tab  = (unsigned*)sm;
    int*      scnt = (int*)(sm + TABSZ * 4);

    const int t = threadIdx.x;
    const int f = blockIdx.x, b = blockIdx.y;
    const float4* col4 = (const float4*)(g_cols + ((size_t)b * FF + f) * SS);

#pragma unroll
    for (int k = 0; k < TABSZ / 256; k++) tab[k * 256 + t] = HEMPTY;
    if (t == 0) scnt[0] = 0;

#pragma unroll 1
    for (int half = 0; half < 2; half++) {
        // 8 values per thread, coalesced
        unsigned v[8];
        unsigned p[8];
#pragma unroll
        for (int k = 0; k < 2; k++) {
            const float4 x = __ldg(&col4[half * 512 + k * 256 + t]);
            v[k * 4 + 0] = __float_as_uint(x.x);
            v[k * 4 + 1] = __float_as_uint(x.y);
            v[k * 4 + 2] = __float_as_uint(x.z);
            v[k * 4 + 3] = __float_as_uint(x.w);
        }
#pragma unroll
        for (int k = 0; k < 8; k++) p[k] = hslot(v[k]);
        __syncthreads();                 // table state stable (init or half 0 done)

        if (half == 0) {                 // blind round only on empty table
#pragma unroll
            for (int k = 0; k < 8; k++) tab[p[k]] = v[k];
        }

        unsigned mask = 0xFFu;
        while (__syncthreads_or((int)mask)) {     // prior writes stable
            unsigned wm = 0;
#pragma unroll
            for (int k = 0; k < 8; k++) {
                if (mask & (1u << k)) {
                    unsigned pp = p[k];
                    for (;;) {                    // scan stable snapshot
                        const unsigned u = tab[pp];
                        if (u == v[k]) { mask &= ~(1u << k); break; }
                        if (u == HEMPTY) { wm |= 1u << k; break; }
                        pp = (pp + hstep(v[k])) & TABM;   // double hash
                    }
                    p[k] = pp;
                }
            }
            __syncthreads();                      // reads done before writes
#pragma unroll
            for (int k = 0; k < 8; k++)           // writes target EMPTY slots only
                if (wm & (1u << k)) tab[p[k]] = v[k];
        }
    }

    int cnt = 0;
#pragma unroll
    for (int k = 0; k < TABSZ / (256 * 4); k++) {
        const uint4 u = ((const uint4*)tab)[k * 256 + t];
        cnt += (u.x != HEMPTY) + (u.y != HEMPTY) + (u.z != HEMPTY) + (u.w != HEMPTY);
    }
#pragma unroll
    for (int o = 16; o; o >>= 1) cnt += __shfl_xor_sync(0xFFFFFFFFu, cnt, o);
    if ((t & 31) == 0) atomicAdd(&scnt[0], cnt);
    __syncthreads();
    if (t == 0) g_uniq[b * FF + f] = scnt[0];
}

// ---------------------------------------------------------------------------
// Kernel 4: stats assembly + MLP. Grid (16, 16), 256 threads, 32 feat/CTA.
// ---------------------------------------------------------------------------
#define MS_RED  0
#define MS_SST  (MS_RED + 15 * 32 * 4)        // 1920
#define MS_H    (MS_SST + 32 * 8 * 4)         // +1024
#define MS_W2   (MS_H + 32 * 64 * 4)          // +8192
#define MS_OFF  (MS_W2 + 64 * 128 * 4)        // +32768
#define MSMEM   (MS_OFF + 64)

__global__ void __launch_bounds__(256)
mlp_kernel(const float* __restrict__ w1, const float* __restrict__ b1,
           const float* __restrict__ w2, const float* __restrict__ b2,
           float* __restrict__ out) {
    extern __shared__ unsigned char sm[];
    float* sred  = (float*)(sm + MS_RED);
    float* sst   = (float*)(sm + MS_SST);
    float* sh    = (float*)(sm + MS_H);
    float* sw2   = (float*)(sm + MS_W2);
    int*   soffs = (int*)(sm + MS_OFF);

    const int t    = threadIdx.x;
    const int tile = blockIdx.x, b = blockIdx.y;

    if (t <= NC) soffs[t] = g_offs[b * (NC + 1) + t];
#pragma unroll
    for (int k = 0; k < 32; k++) sw2[k * 256 + t] = __ldg(&w2[k * 256 + t]);

    for (int idx = t; idx < 480; idx += 256) {
        const int qq = idx >> 5, fl = idx & 31;
        sred[qq * 32 + fl] =
            __ldg(&g_fin[((size_t)b * 15 + qq) * FF + tile * 32 + fl]);
    }
    __syncthreads();

    if (t < 32) {
        const int fl = t;
        const float Sf = (float)SS;
        const float sum    = sred[0 * 32 + fl];
        const float sumsq  = sred[1 * 32 + fl];
        const float sumabs = sred[2 * 32 + fl];
        const float mx     = sred[3 * 32 + fl];
        const float nanc   = sred[4 * 32 + fl];
        const float g   = sum / Sf;
        const float var = sumsq / Sf - g * g;
        float between = 0.f;
#pragma unroll
        for (int c = 0; c < NC; c++) {
            const float cntc = (float)(soffs[c + 1] - soffs[c]);
            const float cm = sred[(5 + c) * 32 + fl] / fmaxf(cntc, 1.f);
            const float d = cm - g;
            between += cntc * d * d;
        }
        between /= Sf;
        float st[6];
        st[0] = between / fmaxf(var, 1e-6f);
        st[1] = nanc / Sf;
        st[2] = (float)__ldg(&g_uniq[b * FF + tile * 32 + fl]) / Sf;
        st[3] = var;
        st[4] = sumabs / Sf;
        st[5] = mx;
#pragma unroll
        for (int k = 0; k < 6; k++) {
            float v = st[k];
            if (!isfinite(v)) v = 0.f;
            sst[fl * 8 + k] = v;
        }
    }
    __syncthreads();

#pragma unroll
    for (int r = 0; r < 8; r++) {
        const int idx = r * 256 + t;
        const int f = idx >> 6, j = idx & 63;
        float z = __ldg(&b1[j]);
#pragma unroll
        for (int i = 0; i < 6; i++) z += sst[f * 8 + i] * __ldg(&w1[i * 64 + j]);
        sh[idx] = z * normcdff(z);           // exact GELU
    }
    __syncthreads();

#pragma unroll
    for (int r = 0; r < 16; r++) {
        const int idx = r * 256 + t;
        const int f = idx >> 7, o = idx & 127;
        float z0 = 0.f, z1 = 0.f;
#pragma unroll 16
        for (int j = 0; j < 64; j += 2) {
            z0 += sh[f * 64 + j]     * sw2[j * 128 + o];
            z1 += sh[f * 64 + j + 1] * sw2[(j + 1) * 128 + o];
        }
        out[((size_t)(b * FF) + tile * 32 + f) * 128 + o] =
            z0 + z1 + __ldg(&b2[o]);
    }
}

// ---------------------------------------------------------------------------
extern "C" void kernel_launch(void* const* d_in, const int* in_sizes, int n_in,
                              void* d_out, int out_size) {
    const float* X  = (const float*)d_in[0];
    const int*   y  = (const int*)d_in[1];
    const float* w1 = (const float*)d_in[2];
    const float* b1 = (const float*)d_in[3];
    const float* w2 = (const float*)d_in[4];
    const float* b2 = (const float*)d_in[5];
    float* out = (float*)d_out;

    cudaFuncSetAttribute(stats_kernel,
                         cudaFuncAttributeMaxDynamicSharedMemorySize, SSMEM);
    cudaFuncSetAttribute(stats_kernel,
                         cudaFuncAttributePreferredSharedMemoryCarveout, 100);
    cudaFuncSetAttribute(uniq_kernel,
                         cudaFuncAttributeMaxDynamicSharedMemorySize, USMEM);
    cudaFuncSetAttribute(uniq_kernel,
                         cudaFuncAttributePreferredSharedMemoryCarveout, 100);
    cudaFuncSetAttribute(mlp_kernel,
                         cudaFuncAttributeMaxDynamicSharedMemorySize, MSMEM);

    prep_kernel<<<BB, 256>>>(y);
    stats_kernel<<<dim3(FF / 4, BB), 256, SSMEM>>>(X);
    uniq_kernel<<<dim3(FF, BB), 256, USMEM>>>();
    mlp_kernel<<<dim3(16, BB), 256, MSMEM>>>(w1, b1, w2, b2, out);
}

// round 17
// speedup vs baseline: 2.3170x; 1.1260x over previous
#include <cuda_runtime.h>
#include <math.h>

#define BB 16
#define SS 4096
#define FF 512
#define NC 10
#define TABSZ 8192
#define TABM  8191
#define HEMPTY 0xFFFFFFFFu   // negative-NaN pattern; impossible after canonicalization

// global scratch (static device arrays; no allocation)
__device__ int   g_cnt[BB * NC];               // class histogram per batch
__device__ float g_fin[BB * 15 * FF];          // [b][q][f]
__device__ int   g_uniq[BB * FF];
__device__ float g_cols[(size_t)BB * FF * SS]; // transposed canonical columns

__device__ __forceinline__ unsigned hslot(unsigned x) {
    x *= 2654435761u;
    return (x >> 19) & TABM;
}
// second hash: odd step -> full cycle over power-of-2 table (kills clustering)
__device__ __forceinline__ unsigned hstep(unsigned x) {
    x *= 0x9E3779B1u;
    return ((x >> 16) | 1u) & TABM;
}

// ---------------------------------------------------------------------------
// Kernel 1: class histogram per batch (predicated, atomic-free)
// ---------------------------------------------------------------------------
__global__ void prep_kernel(const int* __restrict__ y) {
    __shared__ int red[NC][8];
    const int b = blockIdx.x;
    const int t = threadIdx.x;
    const int lane = t & 31, warp = t >> 5;

    int cnt[NC];
#pragma unroll
    for (int c = 0; c < NC; c++) cnt[c] = 0;
#pragma unroll
    for (int j = 0; j < 16; j++) {
        const int yv = __ldg(&y[b * SS + j * 256 + t]);
#pragma unroll
        for (int c = 0; c < NC; c++) cnt[c] += (yv == c);
    }
#pragma unroll
    for (int c = 0; c < NC; c++) {
        int v = cnt[c];
#pragma unroll
        for (int o = 16; o; o >>= 1) v += __shfl_xor_sync(0xFFFFFFFFu, v, o);
        if (lane == 0) red[c][warp] = v;
    }
    __syncthreads();
    if (t < NC) {
        int v = 0;
#pragma unroll
        for (int w = 0; w < 8; w++) v += red[t][w];
        g_cnt[b * NC + t] = v;
    }
}

// ---------------------------------------------------------------------------
// Kernel 2: stats kernel — grid (FF/4, BB), 256 threads, 3 CTAs/SM.
// Single X pass: 5 stats + 10 PREDICATED class sums, all in registers.
// Writes canonical columns to g_cols directly (coalesced). No perm, no vals.
// ---------------------------------------------------------------------------
__global__ void __launch_bounds__(256, 3)
stats_kernel(const float* __restrict__ X, const int* __restrict__ y) {
    __shared__ float red[60 * 8];

    const int t  = threadIdx.x;
    const int fg = blockIdx.x, b = blockIdx.y;
    const int lane = t & 31, warp = t >> 5;

    const float4* Xb = (const float4*)(X + (size_t)b * SS * FF);
    const int*    yb = y + b * SS;

    float s0[4] = {0,0,0,0}, s1[4] = {0,0,0,0}, s2[4] = {0,0,0,0};
    float s3[4] = {0,0,0,0}, s4[4] = {0,0,0,0};
    float cls[NC][4];
#pragma unroll
    for (int c = 0; c < NC; c++)
#pragma unroll
        for (int f = 0; f < 4; f++) cls[c][f] = 0.f;

#pragma unroll 4
    for (int k = 0; k < 16; k++) {
        const int s = k * 256 + t;
        const float4 x = __ldg(&Xb[(size_t)s * (FF / 4) + fg]);
        const int yv = __ldg(&yb[s]);
        float xv[4] = {x.x, x.y, x.z, x.w};
#pragma unroll
        for (int f = 0; f < 4; f++) {
            float v = xv[f];
            const bool isn = (v != v);
            v = isn ? 0.f : v;
            v = (v == 0.f) ? 0.f : v;        // -0 -> +0
            const float a = fabsf(v);
            s0[f] += v;
            s1[f] += v * v;
            s2[f] += a;
            s3[f]  = fmaxf(s3[f], a);
            s4[f] += isn ? 1.f : 0.f;
#pragma unroll
            for (int c = 0; c < NC; c++)     // predicated: static indices only
                cls[c][f] += (yv == c) ? v : 0.f;
            // transposed canonical column write, coalesced over t
            g_cols[((size_t)b * FF + fg * 4 + f) * SS + s] = v;
        }
    }

    // reduce 60 quantities: q = qq*4+f ; qq 0..4 stats, 5..14 class sums
#pragma unroll
    for (int q = 0; q < 60; q++) {
        const int qq = q >> 2, f = q & 3;
        float v;
        if (qq == 0)      v = s0[f];
        else if (qq == 1) v = s1[f];
        else if (qq == 2) v = s2[f];
        else if (qq == 3) v = s3[f];
        else if (qq == 4) v = s4[f];
        else              v = cls[qq - 5][f];
        const bool ismax = (qq == 3);
#pragma unroll
        for (int o = 16; o; o >>= 1) {
            float w = __shfl_xor_sync(0xFFFFFFFFu, v, o);
            v = ismax ? fmaxf(v, w) : (v + w);
        }
        if (lane == 0) red[q * 8 + warp] = v;
    }
    __syncthreads();
    if (t < 60) {
        const int qq = t >> 2, f = t & 3;
        const bool ismax = (qq == 3);
        float v = red[t * 8];
#pragma unroll
        for (int w = 1; w < 8; w++)
            v = ismax ? fmaxf(v, red[t * 8 + w]) : (v + red[t * 8 + w]);
        g_fin[((size_t)b * 15 + qq) * FF + fg * 4 + f] = v;
    }
}

// ---------------------------------------------------------------------------
// Kernel 3: uniq kernel — one CTA per (f, b), 256 threads, 33KB smem,
// 6 CTAs/SM. Two insert halves; serial verify-scan with double hashing.
// (unchanged from the 326us best)
// ---------------------------------------------------------------------------
#define USMEM (TABSZ * 4 + 16)

__global__ void __launch_bounds__(256, 6)
uniq_kernel() {
    extern __shared__ unsigned char sm[];
    unsigned* tab  = (unsigned*)sm;
    int*      scnt = (int*)(sm + TABSZ * 4);

    const int t = threadIdx.x;
    const int f = blockIdx.x, b = blockIdx.y;
    const float4* col4 = (const float4*)(g_cols + ((size_t)b * FF + f) * SS);

#pragma unroll
    for (int k = 0; k < TABSZ / 256; k++) tab[k * 256 + t] = HEMPTY;
    if (t == 0) scnt[0] = 0;

#pragma unroll 1
    for (int half = 0; half < 2; half++) {
        unsigned v[8];
        unsigned p[8];
#pragma unroll
        for (int k = 0; k < 2; k++) {
            const float4 x = __ldg(&col4[half * 512 + k * 256 + t]);
            v[k * 4 + 0] = __float_as_uint(x.x);
            v[k * 4 + 1] = __float_as_uint(x.y);
            v[k * 4 + 2] = __float_as_uint(x.z);
            v[k * 4 + 3] = __float_as_uint(x.w);
        }
#pragma unroll
        for (int k = 0; k < 8; k++) p[k] = hslot(v[k]);
        __syncthreads();                 // table state stable (init or half 0 done)

        if (half == 0) {                 // blind round only on empty table
#pragma unroll
            for (int k = 0; k < 8; k++) tab[p[k]] = v[k];
        }

        unsigned mask = 0xFFu;
        while (__syncthreads_or((int)mask)) {     // prior writes stable
            unsigned wm = 0;
#pragma unroll
            for (int k = 0; k < 8; k++) {
                if (mask & (1u << k)) {
                    unsigned pp = p[k];
                    for (;;) {                    // scan stable snapshot
                        const unsigned u = tab[pp];
                        if (u == v[k]) { mask &= ~(1u << k); break; }
                        if (u == HEMPTY) { wm |= 1u << k; break; }
                        pp = (pp + hstep(v[k])) & TABM;   // double hash
                    }
                    p[k] = pp;
                }
            }
            __syncthreads();                      // reads done before writes
#pragma unroll
            for (int k = 0; k < 8; k++)           // writes target EMPTY slots only
                if (wm & (1u << k)) tab[p[k]] = v[k];
        }
    }

    int cnt = 0;
#pragma unroll
    for (int k = 0; k < TABSZ / (256 * 4); k++) {
        const uint4 u = ((const uint4*)tab)[k * 256 + t];
        cnt += (u.x != HEMPTY) + (u.y != HEMPTY) + (u.z != HEMPTY) + (u.w != HEMPTY);
    }
#pragma unroll
    for (int o = 16; o; o >>= 1) cnt += __shfl_xor_sync(0xFFFFFFFFu, cnt, o);
    if ((t & 31) == 0) atomicAdd(&scnt[0], cnt);
    __syncthreads();
    if (t == 0) g_uniq[b * FF + f] = scnt[0];
}

// ---------------------------------------------------------------------------
// Kernel 4: stats assembly + MLP. Grid (16, 16), 256 threads, 32 feat/CTA.
// ---------------------------------------------------------------------------
#define MS_RED  0
#define MS_SST  (MS_RED + 15 * 32 * 4)        // 1920
#define MS_H    (MS_SST + 32 * 8 * 4)         // +1024
#define MS_W2   (MS_H + 32 * 64 * 4)          // +8192
#define MS_OFF  (MS_W2 + 64 * 128 * 4)        // +32768
#define MSMEM   (MS_OFF + 64)

__global__ void __launch_bounds__(256)
mlp_kernel(const float* __restrict__ w1, const float* __restrict__ b1,
           const float* __restrict__ w2, const float* __restrict__ b2,
           float* __restrict__ out) {
    extern __shared__ unsigned char sm[];
    float* sred  = (float*)(sm + MS_RED);
    float* sst   = (float*)(sm + MS_SST);
    float* sh    = (float*)(sm + MS_H);
    float* sw2   = (float*)(sm + MS_W2);
    int*   scls  = (int*)(sm + MS_OFF);

    const int t    = threadIdx.x;
    const int tile = blockIdx.x, b = blockIdx.y;

    if (t < NC) scls[t] = g_cnt[b * NC + t];
#pragma unroll
    for (int k = 0; k < 32; k++) sw2[k * 256 + t] = __ldg(&w2[k * 256 + t]);

    for (int idx = t; idx < 480; idx += 256) {
        const int qq = idx >> 5, fl = idx & 31;
        sred[qq * 32 + fl] =
            __ldg(&g_fin[((size_t)b * 15 + qq) * FF + tile * 32 + fl]);
    }
    __syncthreads();

    if (t < 32) {
        const int fl = t;
        const float Sf = (float)SS;
        const float sum    = sred[0 * 32 + fl];
        const float sumsq  = sred[1 * 32 + fl];
        const float sumabs = sred[2 * 32 + fl];
        const float mx     = sred[3 * 32 + fl];
        const float nanc   = sred[4 * 32 + fl];
        const float g   = sum / Sf;
        const float var = sumsq / Sf - g * g;
        float between = 0.f;
#pragma unroll
        for (int c = 0; c < NC; c++) {
            const float cntc = (float)scls[c];
            const float cm = sred[(5 + c) * 32 + fl] / fmaxf(cntc, 1.f);
            const float d = cm - g;
            between += cntc * d * d;
        }
        between /= Sf;
        float st[6];
        st[0] = between / fmaxf(var, 1e-6f);
        st[1] = nanc / Sf;
        st[2] = (float)__ldg(&g_uniq[b * FF + tile * 32 + fl]) / Sf;
        st[3] = var;
        st[4] = sumabs / Sf;
        st[5] = mx;
#pragma unroll
        for (int k = 0; k < 6; k++) {
            float v = st[k];
            if (!isfinite(v)) v = 0.f;
            sst[fl * 8 + k] = v;
        }
    }
    __syncthreads();

#pragma unroll
    for (int r = 0; r < 8; r++) {
        const int idx = r * 256 + t;
        const int f = idx >> 6, j = idx & 63;
        float z = __ldg(&b1[j]);
#pragma unroll
        for (int i = 0; i < 6; i++) z += sst[f * 8 + i] * __ldg(&w1[i * 64 + j]);
        sh[idx] = z * normcdff(z);           // exact GELU
    }
    __syncthreads();

#pragma unroll
    for (int r = 0; r < 16; r++) {
        const int idx = r * 256 + t;
        const int f = idx >> 7, o = idx & 127;
        float z0 = 0.f, z1 = 0.f;
#pragma unroll 16
        for (int j = 0; j < 64; j += 2) {
            z0 += sh[f * 64 + j]     * sw2[j * 128 + o];
            z1 += sh[f * 64 + j + 1] * sw2[(j + 1) * 128 + o];
        }
        out[((size_t)(b * FF) + tile * 32 + f) * 128 + o] =
            z0 + z1 + __ldg(&b2[o]);
    }
}

// ---------------------------------------------------------------------------
extern "C" void kernel_launch(void* const* d_in, const int* in_sizes, int n_in,
                              void* d_out, int out_size) {
    const float* X  = (const float*)d_in[0];
    const int*   y  = (const int*)d_in[1];
    const float* w1 = (const float*)d_in[2];
    const float* b1 = (const float*)d_in[3];
    const float* w2 = (const float*)d_in[4];
    const float* b2 = (const float*)d_in[5];
    float* out = (float*)d_out;

    cudaFuncSetAttribute(uniq_kernel,
                         cudaFuncAttributeMaxDynamicSharedMemorySize, USMEM);
    cudaFuncSetAttribute(uniq_kernel,
                         cudaFuncAttributePreferredSharedMemoryCarveout, 100);
    cudaFuncSetAttribute(mlp_kernel,
                         cudaFuncAttributeMaxDynamicSharedMemorySize, MSMEM);

    prep_kernel<<<BB, 256>>>(y);
    stats_kernel<<<dim3(FF / 4, BB), 256>>>(X, y);
    uniq_kernel<<<dim3(FF, BB), 256, USMEM>>>();
    mlp_kernel<<<dim3(16, BB), 256, MSMEM>>>(w1, b1, w2, b2, out);
}